// round 1
// baseline (speedup 1.0000x reference)
#include <cuda_runtime.h>

#define NN 8192
#define FF 64
#define BB 4

// 8 MB ping-pong scratch for the inter-layer activation (allocation-free rule).
__device__ float g_scratch[BB * NN * FF];

// One GCN layer: Zout[b] = relu( (A @ Zin[b]) @ W ),  A:[N,N], Z:[N,F], W:[F,F]
// Block: 256 threads (16x16), computes a 64(M) x 64(F) tile of H for one batch,
// then applies the 64x64 W multiply + ReLU in shared memory.
__global__ __launch_bounds__(256) void gcn_layer_kernel(
    const float* __restrict__ A,
    const float* __restrict__ Zin,
    const float* __restrict__ W,
    float* __restrict__ Zout)
{
    // smem plan:
    //   main loop : As[16][68] (A tile, transposed, padded) + Zs[16][64]
    //   epilogue  : Hs[64][68] + Ws[64][64]   (reuses the same buffer)
    __shared__ float smem[64 * 68 + 64 * 64];  // 33792 B

    float* As = smem;              // [16][68]  As[kk][m]
    float* Zs = smem + 16 * 68;    // [16][64]  Zs[kk][f]

    const int tid = threadIdx.x;
    const int tx  = tid & 15;      // 0..15 -> F columns (x4)
    const int ty  = tid >> 4;      // 0..15 -> M rows    (x4)
    const int b   = blockIdx.y;
    const int m0  = blockIdx.x * 64;

    const float* Ab = A   + (size_t)m0 * NN;
    const float* Zb = Zin + (size_t)b * NN * FF;

    // A tile loader: one float4 per thread. row 0..63, k-quad 0..3
    const int a_row = tid >> 2;
    const int a_kq  = (tid & 3) * 4;
    // Z tile loader: one float4 per thread. k-row 0..15, f-quad 0..15
    const int z_kr  = tid >> 4;
    const int z_f   = (tid & 15) * 4;

    float acc[4][4] = {};

    for (int k = 0; k < NN; k += 16) {
        // global -> shared
        float4 av = *(const float4*)&Ab[(size_t)a_row * NN + (k + a_kq)];
        float4 zv = *(const float4*)&Zb[(size_t)(k + z_kr) * FF + z_f];

        As[(a_kq + 0) * 68 + a_row] = av.x;
        As[(a_kq + 1) * 68 + a_row] = av.y;
        As[(a_kq + 2) * 68 + a_row] = av.z;
        As[(a_kq + 3) * 68 + a_row] = av.w;
        *(float4*)&Zs[z_kr * 64 + z_f] = zv;
        __syncthreads();

        #pragma unroll
        for (int kk = 0; kk < 16; kk++) {
            float4 a = *(const float4*)&As[kk * 68 + ty * 4];
            float4 z = *(const float4*)&Zs[kk * 64 + tx * 4];
            float ar[4] = {a.x, a.y, a.z, a.w};
            float zr[4] = {z.x, z.y, z.z, z.w};
            #pragma unroll
            for (int i = 0; i < 4; i++)
                #pragma unroll
                for (int j = 0; j < 4; j++)
                    acc[i][j] += ar[i] * zr[j];
        }
        __syncthreads();
    }

    // ---- epilogue: Hs = acc (block-wide), out = relu(Hs @ W) ----
    float* Hs = smem;              // [64][68]
    float* Ws = smem + 64 * 68;    // [64][64]

    #pragma unroll
    for (int i = 0; i < 4; i++) {
        float4 v = make_float4(acc[i][0], acc[i][1], acc[i][2], acc[i][3]);
        *(float4*)&Hs[(ty * 4 + i) * 68 + tx * 4] = v;
    }
    // load W (4096 floats) cooperatively
    for (int i = tid; i < (FF * FF) / 4; i += 256)
        ((float4*)Ws)[i] = ((const float4*)W)[i];
    __syncthreads();

    #pragma unroll
    for (int i = 0; i < 4; i++) {
        const int m = ty * 4 + i;
        const float* hrow = &Hs[m * 68];
        float o0 = 0.f, o1 = 0.f, o2 = 0.f, o3 = 0.f;
        #pragma unroll
        for (int f = 0; f < FF; f++) {
            float h  = hrow[f];
            float4 w = *(const float4*)&Ws[f * 64 + tx * 4];
            o0 += h * w.x;
            o1 += h * w.y;
            o2 += h * w.z;
            o3 += h * w.w;
        }
        o0 = fmaxf(o0, 0.f);
        o1 = fmaxf(o1, 0.f);
        o2 = fmaxf(o2, 0.f);
        o3 = fmaxf(o3, 0.f);
        *(float4*)&Zout[(size_t)b * NN * FF + (size_t)(m0 + m) * FF + tx * 4] =
            make_float4(o0, o1, o2, o3);
    }
}

extern "C" void kernel_launch(void* const* d_in, const int* in_sizes, int n_in,
                              void* d_out, int out_size)
{
    // metadata order: x [B*N*F f32], t [int], net_params [L*F*F f32], A [N*N f32]
    const float* x   = (const float*)d_in[0];
    const float* net = (const float*)d_in[2];
    const float* A   = (const float*)d_in[3];
    float* out       = (float*)d_out;

    float* scratch = nullptr;
    cudaGetSymbolAddress((void**)&scratch, g_scratch);

    dim3 grid(NN / 64, BB);
    dim3 block(256);

    // layer 0: x -> scratch
    gcn_layer_kernel<<<grid, block>>>(A, x, net, scratch);
    // layer 1: scratch -> out
    gcn_layer_kernel<<<grid, block>>>(A, scratch, net + FF * FF, out);
}

// round 3
// speedup vs baseline: 2.8397x; 2.8397x over previous
#include <cuda_runtime.h>

#define NN 8192
#define FF 64
#define BB 4
#define KT 32            // K tile per mainloop iter
#define AST 36           // A smem row stride (floats) -> conflict-free frag loads
#define ZST 72           // Z smem row stride (floats) -> conflict-free frag loads
#define HST 68           // H smem row stride for epilogue
#define NITER (NN / KT)  // 256

__device__ float g_scratch[BB * NN * FF];

__device__ __forceinline__ void split(float x, unsigned& hi, unsigned& lo) {
    unsigned h;
    asm("cvt.rna.tf32.f32 %0, %1;" : "=r"(h) : "f"(x));
    hi = h;
    float hf = __uint_as_float(h);
    float res = x - hf;
    unsigned l;
    asm("cvt.rna.tf32.f32 %0, %1;" : "=r"(l) : "f"(res));
    lo = l;
}

__device__ __forceinline__ void mma_tf32(float* d, const unsigned* a, const unsigned* b) {
    asm volatile(
        "mma.sync.aligned.m16n8k8.row.col.f32.tf32.tf32.f32 "
        "{%0,%1,%2,%3},{%4,%5,%6,%7},{%8,%9},{%0,%1,%2,%3};"
        : "+f"(d[0]), "+f"(d[1]), "+f"(d[2]), "+f"(d[3])
        : "r"(a[0]), "r"(a[1]), "r"(a[2]), "r"(a[3]), "r"(b[0]), "r"(b[1]));
}

__device__ __forceinline__ void cp16(void* smem_dst, const void* gsrc) {
    unsigned dst = (unsigned)__cvta_generic_to_shared(smem_dst);
    asm volatile("cp.async.cg.shared.global [%0], [%1], 16;\n" :: "r"(dst), "l"(gsrc));
}

// Load one K-tile: A[128][32] and Z[32][64] into padded smem buffers.
__device__ __forceinline__ void load_tiles(float* Asb, float* Zsb,
                                           const float* Ab, const float* Zb,
                                           int k, int tid)
{
    #pragma unroll
    for (int i = 0; i < 4; i++) {
        int idx = tid + i * 256;
        int row = idx >> 3;            // 0..127
        int c4  = (idx & 7) << 2;      // 0,4,..,28
        cp16(&Asb[row * AST + c4], &Ab[(size_t)row * NN + k + c4]);
    }
    #pragma unroll
    for (int i = 0; i < 2; i++) {
        int idx = tid + i * 256;
        int kr = idx >> 4;             // 0..31
        int c4 = (idx & 15) << 2;      // 0,4,..,60
        cp16(&Zsb[kr * ZST + c4], &Zb[(size_t)(k + kr) * FF + c4]);
    }
}

// 3-product split-TF32 MMA over NK k-steps of 8.
// A operand: Asb[row][k] stride ast;  B operand: Zsb[k][n] stride zst.
template<int NK>
__device__ __forceinline__ void mma_block(const float* __restrict__ Asb, int ast,
                                          const float* __restrict__ Zsb, int zst,
                                          int wm, int wn, int g, int t,
                                          float acc[2][4][4])
{
    #pragma unroll
    for (int kk = 0; kk < NK; kk++) {
        const int k8 = kk * 8;
        unsigned ah[2][4], al[2][4];
        #pragma unroll
        for (int mi = 0; mi < 2; mi++) {
            int m = wm + mi * 16;
            split(Asb[(m + g    ) * ast + k8 + t    ], ah[mi][0], al[mi][0]);
            split(Asb[(m + g + 8) * ast + k8 + t    ], ah[mi][1], al[mi][1]);
            split(Asb[(m + g    ) * ast + k8 + t + 4], ah[mi][2], al[mi][2]);
            split(Asb[(m + g + 8) * ast + k8 + t + 4], ah[mi][3], al[mi][3]);
        }
        unsigned bh[4][2], bl[4][2];
        #pragma unroll
        for (int ni = 0; ni < 4; ni++) {
            int n = wn + ni * 8 + g;
            split(Zsb[(k8 + t    ) * zst + n], bh[ni][0], bl[ni][0]);
            split(Zsb[(k8 + t + 4) * zst + n], bh[ni][1], bl[ni][1]);
        }
        #pragma unroll
        for (int mi = 0; mi < 2; mi++)
            #pragma unroll
            for (int ni = 0; ni < 4; ni++) {
                mma_tf32(acc[mi][ni], ah[mi], bh[ni]);  // hi*hi
                mma_tf32(acc[mi][ni], al[mi], bh[ni]);  // lo*hi
                mma_tf32(acc[mi][ni], ah[mi], bl[ni]);  // hi*lo
            }
    }
}

// One GCN layer: Zout[b] = relu( (A @ Zin[b]) @ W )
// CTA: 128(M) x 64(N=F) tile, 8 warps of 32x32 warp-tiles, K-tiled by 32.
__global__ __launch_bounds__(256, 2) void gcn_layer_kernel(
    const float* __restrict__ A,
    const float* __restrict__ Zin,
    const float* __restrict__ W,
    float* __restrict__ Zout)
{
    extern __shared__ float smem[];
    float* As0 = smem;
    float* As1 = smem + 128 * AST;
    float* Zs0 = smem + 2 * 128 * AST;
    float* Zs1 = Zs0 + KT * ZST;
    float* Asb[2] = { As0, As1 };
    float* Zsb[2] = { Zs0, Zs1 };

    const int tid  = threadIdx.x;
    const int lane = tid & 31;
    const int warp = tid >> 5;
    const int g = lane >> 2;
    const int t = lane & 3;
    const int wm = (warp & 3) * 32;    // warp M offset in 128
    const int wn = (warp >> 2) * 32;   // warp N offset in 64

    const int b  = blockIdx.y;
    const int m0 = blockIdx.x * 128;
    const float* Ab = A   + (size_t)m0 * NN;
    const float* Zb = Zin + (size_t)b * NN * FF;

    float acc[2][4][4];
    #pragma unroll
    for (int mi = 0; mi < 2; mi++)
        #pragma unroll
        for (int ni = 0; ni < 4; ni++)
            #pragma unroll
            for (int j = 0; j < 4; j++)
                acc[mi][ni][j] = 0.f;

    // ---- pipelined mainloop: H = A_tile @ Z ----
    load_tiles(Asb[0], Zsb[0], Ab, Zb, 0, tid);
    asm volatile("cp.async.commit_group;\n" ::);

    for (int kt = 0; kt < NITER; kt++) {
        const int nxt = kt + 1;
        if (nxt < NITER) {
            load_tiles(Asb[nxt & 1], Zsb[nxt & 1], Ab, Zb, nxt * KT, tid);
            asm volatile("cp.async.commit_group;\n" ::);
            asm volatile("cp.async.wait_group 1;\n" ::);
        } else {
            asm volatile("cp.async.wait_group 0;\n" ::);
        }
        __syncthreads();
        mma_block<4>(Asb[kt & 1], AST, Zsb[kt & 1], ZST, wm, wn, g, t, acc);
        __syncthreads();
    }

    // ---- epilogue: stage H to smem, out = relu(H @ W) via tensor cores ----
    float* Hs = smem;                   // 128 x HST, fits in A double-buffer region
    float* Ws = smem + 2 * 128 * AST;   // 64 x ZST,  fits in Z double-buffer region

    #pragma unroll
    for (int mi = 0; mi < 2; mi++)
        #pragma unroll
        for (int ni = 0; ni < 4; ni++) {
            int r = wm + mi * 16 + g;
            int c = wn + ni * 8 + 2 * t;
            Hs[(r    ) * HST + c    ] = acc[mi][ni][0];
            Hs[(r    ) * HST + c + 1] = acc[mi][ni][1];
            Hs[(r + 8) * HST + c    ] = acc[mi][ni][2];
            Hs[(r + 8) * HST + c + 1] = acc[mi][ni][3];
        }
    for (int i = tid; i < FF * FF; i += 256) {
        int f = i >> 6, c = i & 63;
        Ws[f * ZST + c] = W[i];
    }
    __syncthreads();

    #pragma unroll
    for (int mi = 0; mi < 2; mi++)
        #pragma unroll
        for (int ni = 0; ni < 4; ni++)
            #pragma unroll
            for (int j = 0; j < 4; j++)
                acc[mi][ni][j] = 0.f;

    mma_block<8>(Hs, HST, Ws, ZST, wm, wn, g, t, acc);

    float* outp = Zout + (size_t)b * NN * FF + (size_t)m0 * FF;
    #pragma unroll
    for (int mi = 0; mi < 2; mi++)
        #pragma unroll
        for (int ni = 0; ni < 4; ni++) {
            int r = wm + mi * 16 + g;
            int c = wn + ni * 8 + 2 * t;
            float2 v0 = make_float2(fmaxf(acc[mi][ni][0], 0.f), fmaxf(acc[mi][ni][1], 0.f));
            float2 v1 = make_float2(fmaxf(acc[mi][ni][2], 0.f), fmaxf(acc[mi][ni][3], 0.f));
            *(float2*)&outp[(size_t)(r    ) * FF + c] = v0;
            *(float2*)&outp[(size_t)(r + 8) * FF + c] = v1;
        }
}

extern "C" void kernel_launch(void* const* d_in, const int* in_sizes, int n_in,
                              void* d_out, int out_size)
{
    const float* x   = (const float*)d_in[0];
    const float* net = (const float*)d_in[2];
    const float* A   = (const float*)d_in[3];
    float* out       = (float*)d_out;

    float* scratch = nullptr;
    cudaGetSymbolAddress((void**)&scratch, g_scratch);

    const int smem_bytes = (2 * 128 * AST + 2 * KT * ZST) * sizeof(float);  // 55296
    cudaFuncSetAttribute(gcn_layer_kernel,
                         cudaFuncAttributeMaxDynamicSharedMemorySize, smem_bytes);

    dim3 grid(NN / 128, BB);
    dim3 block(256);

    gcn_layer_kernel<<<grid, block, smem_bytes>>>(A, x, net, scratch);
    gcn_layer_kernel<<<grid, block, smem_bytes>>>(A, scratch, net + FF * FF, out);
}

// round 6
// speedup vs baseline: 4.7609x; 1.6766x over previous
#include <cuda_runtime.h>
#include <cuda_bf16.h>
#include <cstdint>

#define NN 8192
#define FF 64
#define BB 4
#define NCOL 256             // fused N = BB*FF
#define KHALF 4096           // K per ksplit
#define KT 32                // K per mainloop tile
#define NITER (KHALF / KT)   // 128
#define MT 128
#define RST 80               // smem row stride bytes (32 bf16 = 64B data + pad)

// Precomputed bf16 splits + partials + mid activation (allocation-free rule).
__device__ unsigned short g_A0[(size_t)NN * NN];
__device__ unsigned short g_A1[(size_t)NN * NN];
__device__ unsigned short g_Z0[(size_t)NCOL * NN];   // [n=b*64+f][k], n-major
__device__ unsigned short g_Z1s[(size_t)NCOL * NN];
__device__ float g_P[2][(size_t)NN * NCOL];
__device__ float g_Zmid[(size_t)BB * NN * FF];

// smem: per buffer: Ahi(10240) Alo(10240) Bhi(10240) Blo(10240) = 40960; x2 buffers
#define BUFB 40960
#define SMEM_BYTES (2 * BUFB)

__device__ __forceinline__ void cp16(uint32_t dst, const void* gsrc) {
    asm volatile("cp.async.cg.shared.global [%0], [%1], 16;\n" :: "r"(dst), "l"(gsrc));
}
__device__ __forceinline__ uint32_t lds32(uint32_t a) {
    uint32_t v;
    asm volatile("ld.shared.b32 %0, [%1];" : "=r"(v) : "r"(a));
    return v;
}
__device__ __forceinline__ void mma_bf16(float* d, const uint32_t* a, const uint32_t* b) {
    asm volatile(
        "mma.sync.aligned.m16n8k16.row.col.f32.bf16.bf16.f32 "
        "{%0,%1,%2,%3},{%4,%5,%6,%7},{%8,%9},{%0,%1,%2,%3};"
        : "+f"(d[0]), "+f"(d[1]), "+f"(d[2]), "+f"(d[3])
        : "r"(a[0]), "r"(a[1]), "r"(a[2]), "r"(a[3]), "r"(b[0]), "r"(b[1]));
}
__device__ __forceinline__ void bsplit(float x, unsigned short& hi, unsigned short& lo) {
    __nv_bfloat16 h = __float2bfloat16_rn(x);
    float r = x - __bfloat162float(h);
    __nv_bfloat16 l = __float2bfloat16_rn(r);
    hi = *(unsigned short*)&h;
    lo = *(unsigned short*)&l;
}

// ---- split A (fp32 -> bf16 hi/lo), once per launch ----
__global__ __launch_bounds__(256) void split_a_kernel(const float* __restrict__ A)
{
    size_t i4 = (size_t)blockIdx.x * 256 + threadIdx.x;
    const size_t n4 = (size_t)NN * NN / 4;
    size_t stride = (size_t)gridDim.x * 256;
    for (; i4 < n4; i4 += stride) {
        float4 v = ((const float4*)A)[i4];
        ushort4 h, l;
        bsplit(v.x, h.x, l.x); bsplit(v.y, h.y, l.y);
        bsplit(v.z, h.z, l.z); bsplit(v.w, h.w, l.w);
        ((ushort4*)g_A0)[i4] = h;
        ((ushort4*)g_A1)[i4] = l;
    }
}

// ---- split + transpose Z: in[b][k][f] fp32 -> g_Z0/g_Z1s[b*64+f][k] bf16 ----
__global__ __launch_bounds__(256) void split_z_kernel(const float* __restrict__ Zin)
{
    __shared__ float s[64 * 65];
    const int b = blockIdx.y;
    const int k0 = blockIdx.x * 64;
    const int tid = threadIdx.x;
    #pragma unroll
    for (int i = 0; i < 16; i++) {
        int idx = tid + i * 256;
        int kr = idx >> 6, f = idx & 63;
        s[kr * 65 + f] = Zin[((size_t)b * NN + k0 + kr) * FF + f];
    }
    __syncthreads();
    #pragma unroll
    for (int i = 0; i < 16; i++) {
        int idx = tid + i * 256;
        int f = idx >> 6, kl = idx & 63;
        unsigned short h, l;
        bsplit(s[kl * 65 + f], h, l);
        size_t o = (size_t)(b * FF + f) * NN + k0 + kl;
        g_Z0[o] = h;
        g_Z1s[o] = l;
    }
}

// ---- GEMM: P[kh] += A[m-tile, khalf] @ Zfused  (3-product bf16 split) ----
__global__ __launch_bounds__(256, 2) void gemm_kernel(float* __restrict__ P)
{
    extern __shared__ char smem[];
    const uint32_t sb = (uint32_t)__cvta_generic_to_shared(smem);
    const int tid = threadIdx.x;
    const int lane = tid & 31;
    const int warp = tid >> 5;
    const int g = lane >> 2;
    const int t = lane & 3;
    const int wm = (warp & 3) * 32;
    const int wn = (warp >> 2) * 64;

    const int m0 = blockIdx.x * MT;
    const int n0 = blockIdx.y * 128;   // fused col offset
    const int kh = blockIdx.z;
    const size_t kbase = (size_t)kh * KHALF;

    float acc[2][8][4] = {};

    // --- tile loader ---
    auto load_tile = [&](int buf, int kt) {
        const size_t k0 = kbase + (size_t)kt * KT;
        const uint32_t d0 = sb + buf * BUFB;
        #pragma unroll
        for (int s = 0; s < 2; s++) {
            const unsigned short* src = s ? g_A1 : g_A0;
            #pragma unroll
            for (int i = 0; i < 2; i++) {
                int cidx = tid + i * 256;        // 0..511
                int r = cidx >> 2, c = cidx & 3;
                cp16(d0 + s * 10240 + r * RST + c * 16,
                     src + (size_t)(m0 + r) * NN + k0 + c * 8);
            }
        }
        #pragma unroll
        for (int s = 0; s < 2; s++) {
            const unsigned short* src = s ? g_Z1s : g_Z0;
            #pragma unroll
            for (int i = 0; i < 2; i++) {
                int cidx = tid + i * 256;
                int r = cidx >> 2, c = cidx & 3;
                cp16(d0 + 20480 + s * 10240 + r * RST + c * 16,
                     src + (size_t)(n0 + r) * NN + k0 + c * 8);
            }
        }
    };

    load_tile(0, 0);
    asm volatile("cp.async.commit_group;\n" ::);

    for (int kt = 0; kt < NITER; kt++) {
        const int buf = kt & 1;
        if (kt + 1 < NITER) {
            load_tile(buf ^ 1, kt + 1);
            asm volatile("cp.async.commit_group;\n" ::);
            asm volatile("cp.async.wait_group 1;\n" ::);
        } else {
            asm volatile("cp.async.wait_group 0;\n" ::);
        }
        __syncthreads();

        const uint32_t ab = sb + buf * BUFB;          // A hi
        const uint32_t bb = ab + 20480;               // B hi
        #pragma unroll
        for (int kk = 0; kk < 2; kk++) {
            const int kbyte = kk * 32;
            uint32_t ah[2][4], al[2][4], bh[8][2], bl[8][2];
            #pragma unroll
            for (int mi = 0; mi < 2; mi++) {
                uint32_t r0 = ab + (wm + mi * 16 + g) * RST + kbyte + 4 * t;
                ah[mi][0] = lds32(r0);
                ah[mi][1] = lds32(r0 + 8 * RST);
                ah[mi][2] = lds32(r0 + 16);
                ah[mi][3] = lds32(r0 + 8 * RST + 16);
            }
            #pragma unroll
            for (int ni = 0; ni < 8; ni++) {
                uint32_t r0 = bb + (wn + ni * 8 + g) * RST + kbyte + 4 * t;
                bh[ni][0] = lds32(r0);
                bh[ni][1] = lds32(r0 + 16);
            }
            #pragma unroll
            for (int mi = 0; mi < 2; mi++)
                #pragma unroll
                for (int ni = 0; ni < 8; ni++)
                    mma_bf16(acc[mi][ni], ah[mi], bh[ni]);   // hi*hi
            #pragma unroll
            for (int ni = 0; ni < 8; ni++) {
                uint32_t r0 = bb + 10240 + (wn + ni * 8 + g) * RST + kbyte + 4 * t;
                bl[ni][0] = lds32(r0);
                bl[ni][1] = lds32(r0 + 16);
            }
            #pragma unroll
            for (int mi = 0; mi < 2; mi++)
                #pragma unroll
                for (int ni = 0; ni < 8; ni++)
                    mma_bf16(acc[mi][ni], ah[mi], bl[ni]);   // hi*lo
            #pragma unroll
            for (int mi = 0; mi < 2; mi++) {
                uint32_t r0 = ab + 10240 + (wm + mi * 16 + g) * RST + kbyte + 4 * t;
                al[mi][0] = lds32(r0);
                al[mi][1] = lds32(r0 + 8 * RST);
                al[mi][2] = lds32(r0 + 16);
                al[mi][3] = lds32(r0 + 8 * RST + 16);
            }
            #pragma unroll
            for (int mi = 0; mi < 2; mi++)
                #pragma unroll
                for (int ni = 0; ni < 8; ni++)
                    mma_bf16(acc[mi][ni], al[mi], bh[ni]);   // lo*hi
        }
        __syncthreads();
    }

    // --- epilogue: partials to P[kh] ---
    float* Pl = P + (size_t)kh * NN * NCOL;
    #pragma unroll
    for (int mi = 0; mi < 2; mi++) {
        const size_t r = (size_t)(m0 + wm + mi * 16 + g);
        #pragma unroll
        for (int ni = 0; ni < 8; ni++) {
            const int c = n0 + wn + ni * 8 + 2 * t;
            *(float2*)&Pl[r * NCOL + c] = make_float2(acc[mi][ni][0], acc[mi][ni][1]);
            *(float2*)&Pl[(r + 8) * NCOL + c] = make_float2(acc[mi][ni][2], acc[mi][ni][3]);
        }
    }
}

// ---- out[b][m][g] = relu( sum_f (P0+P1)[m][b*64+f] * W[f][g] ) ----
#define RM 16
__global__ __launch_bounds__(256) void reduce_w_kernel(
    const float* __restrict__ W, float* __restrict__ Zout)
{
    __shared__ float Hs[RM * 264];
    __shared__ float Ws[FF * FF];
    const int tid = threadIdx.x;
    const int m0 = blockIdx.x * RM;

    const float* P0 = g_P[0];
    const float* P1 = g_P[1];
    for (int i = tid; i < RM * NCOL / 4; i += 256) {
        int row = i >> 6, c4 = (i & 63) * 4;
        size_t gg = (size_t)(m0 + row) * NCOL + c4;
        float4 a = *(const float4*)&P0[gg];
        float4 b = *(const float4*)&P1[gg];
        *(float4*)&Hs[row * 264 + c4] =
            make_float4(a.x + b.x, a.y + b.y, a.z + b.z, a.w + b.w);
    }
    for (int i = tid; i < FF * FF; i += 256) Ws[i] = W[i];
    __syncthreads();

    const int m = tid >> 4;
    const int gq = tid & 15;
    const int b = gq >> 2, fh = (gq & 3) * 16;
    float acc[16] = {};
    const float* hrow = &Hs[m * 264 + b * 64];
    for (int fp = 0; fp < 64; fp++) {
        float h = hrow[fp];
        #pragma unroll
        for (int j = 0; j < 16; j++) acc[j] += h * Ws[fp * 64 + fh + j];
    }
    float* op = Zout + ((size_t)b * NN + (m0 + m)) * FF + fh;
    #pragma unroll
    for (int j = 0; j < 16; j += 4)
        *(float4*)&op[j] = make_float4(fmaxf(acc[j], 0.f), fmaxf(acc[j + 1], 0.f),
                                       fmaxf(acc[j + 2], 0.f), fmaxf(acc[j + 3], 0.f));
}

extern "C" void kernel_launch(void* const* d_in, const int* in_sizes, int n_in,
                              void* d_out, int out_size)
{
    const float* x   = (const float*)d_in[0];
    const float* net = (const float*)d_in[2];
    const float* A   = (const float*)d_in[3];
    float* out       = (float*)d_out;

    float *P = nullptr, *Zmid = nullptr;
    cudaGetSymbolAddress((void**)&P, g_P);
    cudaGetSymbolAddress((void**)&Zmid, g_Zmid);

    cudaFuncSetAttribute(gemm_kernel,
                         cudaFuncAttributeMaxDynamicSharedMemorySize, SMEM_BYTES);

    dim3 ggrid(NN / MT, 2, 2);
    dim3 zgrid(NN / 64, BB);

    split_a_kernel<<<4096, 256>>>(A);
    // layer 0
    split_z_kernel<<<zgrid, 256>>>(x);
    gemm_kernel<<<ggrid, 256, SMEM_BYTES>>>(P);
    reduce_w_kernel<<<NN / RM, 256>>>(net, Zmid);
    // layer 1
    split_z_kernel<<<zgrid, 256>>>(Zmid);
    gemm_kernel<<<ggrid, 256, SMEM_BYTES>>>(P);
    reduce_w_kernel<<<NN / RM, 256>>>(net + FF * FF, out);
}

// round 8
// speedup vs baseline: 5.3499x; 1.1237x over previous
#include <cuda_runtime.h>
#include <cuda_bf16.h>
#include <cstdint>

#define NN 8192
#define FF 64
#define BB 4
#define NCOL 256             // fused N = BB*FF
#define KHALF 4096           // K per ksplit
#define KT 32                // K per mainloop tile
#define NITER (KHALF / KT)   // 128
#define MT 128
#define RST 80               // smem row stride bytes (32 bf16 = 64B + pad)

__device__ unsigned short g_A0[(size_t)NN * NN];
__device__ unsigned short g_A1[(size_t)NN * NN];
__device__ unsigned short g_Z0[(size_t)NCOL * NN];   // [n=b*64+f][k]
__device__ unsigned short g_Z1s[(size_t)NCOL * NN];
__device__ float g_P[2][(size_t)NN * NCOL];
__device__ float g_Zmid[(size_t)BB * NN * FF];

// gemm smem: per buffer Ahi(10240) Alo(10240) Bhi(20480) Blo(20480) = 61440; x2
#define BUFB 61440
#define GEMM_SMEM (2 * BUFB)

__device__ __forceinline__ void cp16(uint32_t dst, const void* gsrc) {
    asm volatile("cp.async.cg.shared.global [%0], [%1], 16;\n" :: "r"(dst), "l"(gsrc));
}
__device__ __forceinline__ uint32_t lds32(uint32_t a) {
    uint32_t v;
    asm volatile("ld.shared.b32 %0, [%1];" : "=r"(v) : "r"(a));
    return v;
}
__device__ __forceinline__ void mma_bf16(float* d, const uint32_t* a, const uint32_t* b) {
    asm volatile(
        "mma.sync.aligned.m16n8k16.row.col.f32.bf16.bf16.f32 "
        "{%0,%1,%2,%3},{%4,%5,%6,%7},{%8,%9},{%0,%1,%2,%3};"
        : "+f"(d[0]), "+f"(d[1]), "+f"(d[2]), "+f"(d[3])
        : "r"(a[0]), "r"(a[1]), "r"(a[2]), "r"(a[3]), "r"(b[0]), "r"(b[1]));
}
__device__ __forceinline__ void bsplit(float x, unsigned short& hi, unsigned short& lo) {
    __nv_bfloat16 h = __float2bfloat16_rn(x);
    float r = x - __bfloat162float(h);
    __nv_bfloat16 l = __float2bfloat16_rn(r);
    hi = *(unsigned short*)&h;
    lo = *(unsigned short*)&l;
}

// ---- split A (fp32 -> bf16 hi/lo), once ----
__global__ __launch_bounds__(256) void split_a_kernel(const float* __restrict__ A)
{
    size_t i4 = (size_t)blockIdx.x * 256 + threadIdx.x;
    const size_t n4 = (size_t)NN * NN / 4;
    size_t stride = (size_t)gridDim.x * 256;
    for (; i4 < n4; i4 += stride) {
        float4 v = ((const float4*)A)[i4];
        ushort4 h, l;
        bsplit(v.x, h.x, l.x); bsplit(v.y, h.y, l.y);
        bsplit(v.z, h.z, l.z); bsplit(v.w, h.w, l.w);
        ((ushort4*)g_A0)[i4] = h;
        ((ushort4*)g_A1)[i4] = l;
    }
}

// ---- split + transpose Z: [b][k][f] fp32 -> [b*64+f][k] bf16 hi/lo ----
__global__ __launch_bounds__(256) void split_z_kernel(const float* __restrict__ Zin)
{
    __shared__ float s[64 * 65];
    const int b = blockIdx.y;
    const int k0 = blockIdx.x * 64;
    const int tid = threadIdx.x;
    #pragma unroll
    for (int i = 0; i < 16; i++) {
        int idx = tid + i * 256;
        int kr = idx >> 6, f = idx & 63;
        s[kr * 65 + f] = Zin[((size_t)b * NN + k0 + kr) * FF + f];
    }
    __syncthreads();
    #pragma unroll
    for (int i = 0; i < 16; i++) {
        int idx = tid + i * 256;
        int f = idx >> 6, kl = idx & 63;
        unsigned short h, l;
        bsplit(s[kl * 65 + f], h, l);
        size_t o = (size_t)(b * FF + f) * NN + k0 + kl;
        g_Z0[o] = h;
        g_Z1s[o] = l;
    }
}

// ---- GEMM: P[kh] = A[m-tile, khalf] @ Zfused  (3-product bf16 split) ----
// CTA 128M x 256N, 8 warps as 2M x 4N (warp tile 64x64), 1 CTA/SM.
__global__ __launch_bounds__(256, 1) void gemm_kernel(float* __restrict__ P)
{
    extern __shared__ char smem[];
    const uint32_t sb = (uint32_t)__cvta_generic_to_shared(smem);
    const int tid = threadIdx.x;
    const int lane = tid & 31;
    const int warp = tid >> 5;
    const int g = lane >> 2;
    const int t = lane & 3;
    const int wm = (warp & 1) * 64;
    const int wn = (warp >> 1) * 64;

    const int m0 = blockIdx.x * MT;
    const int kh = blockIdx.y;
    const size_t kbase = (size_t)kh * KHALF;

    float acc[4][8][4] = {};

    auto load_tile = [&](int buf, int kt) {
        const size_t k0 = kbase + (size_t)kt * KT;
        const uint32_t d0 = sb + buf * BUFB;
        #pragma unroll
        for (int s = 0; s < 2; s++) {
            const unsigned short* src = s ? g_A1 : g_A0;
            #pragma unroll
            for (int i = 0; i < 2; i++) {
                int cidx = tid + i * 256;        // 0..511
                int r = cidx >> 2, c = cidx & 3;
                cp16(d0 + s * 10240 + r * RST + c * 16,
                     src + (size_t)(m0 + r) * NN + k0 + c * 8);
            }
        }
        #pragma unroll
        for (int s = 0; s < 2; s++) {
            const unsigned short* src = s ? g_Z1s : g_Z0;
            #pragma unroll
            for (int i = 0; i < 4; i++) {
                int cidx = tid + i * 256;        // 0..1023
                int r = cidx >> 2, c = cidx & 3;
                cp16(d0 + 20480 + s * 20480 + r * RST + c * 16,
                     src + (size_t)r * NN + k0 + c * 8);
            }
        }
    };

    load_tile(0, 0);
    asm volatile("cp.async.commit_group;\n" ::);

    for (int kt = 0; kt < NITER; kt++) {
        const int buf = kt & 1;
        if (kt + 1 < NITER) {
            load_tile(buf ^ 1, kt + 1);
            asm volatile("cp.async.commit_group;\n" ::);
            asm volatile("cp.async.wait_group 1;\n" ::);
        } else {
            asm volatile("cp.async.wait_group 0;\n" ::);
        }
        __syncthreads();

        const uint32_t ab = sb + buf * BUFB;   // A hi
        const uint32_t bb = ab + 20480;        // B hi
        #pragma unroll
        for (int kk = 0; kk < 2; kk++) {
            const int kbyte = kk * 32;
            uint32_t ah[4][4], bh[8][2];
            #pragma unroll
            for (int mi = 0; mi < 4; mi++) {
                uint32_t r0 = ab + (wm + mi * 16 + g) * RST + kbyte + 4 * t;
                ah[mi][0] = lds32(r0);
                ah[mi][1] = lds32(r0 + 8 * RST);
                ah[mi][2] = lds32(r0 + 16);
                ah[mi][3] = lds32(r0 + 8 * RST + 16);
            }
            #pragma unroll
            for (int ni = 0; ni < 8; ni++) {
                uint32_t r0 = bb + (wn + ni * 8 + g) * RST + kbyte + 4 * t;
                bh[ni][0] = lds32(r0);
                bh[ni][1] = lds32(r0 + 16);
            }
            #pragma unroll
            for (int mi = 0; mi < 4; mi++)
                #pragma unroll
                for (int ni = 0; ni < 8; ni++)
                    mma_bf16(acc[mi][ni], ah[mi], bh[ni]);   // hi*hi
            {
                uint32_t bl[8][2];
                #pragma unroll
                for (int ni = 0; ni < 8; ni++) {
                    uint32_t r0 = bb + 20480 + (wn + ni * 8 + g) * RST + kbyte + 4 * t;
                    bl[ni][0] = lds32(r0);
                    bl[ni][1] = lds32(r0 + 16);
                }
                #pragma unroll
                for (int mi = 0; mi < 4; mi++)
                    #pragma unroll
                    for (int ni = 0; ni < 8; ni++)
                        mma_bf16(acc[mi][ni], ah[mi], bl[ni]);   // hi*lo
            }
            {
                uint32_t al[4][4];
                #pragma unroll
                for (int mi = 0; mi < 4; mi++) {
                    uint32_t r0 = ab + 10240 + (wm + mi * 16 + g) * RST + kbyte + 4 * t;
                    al[mi][0] = lds32(r0);
                    al[mi][1] = lds32(r0 + 8 * RST);
                    al[mi][2] = lds32(r0 + 16);
                    al[mi][3] = lds32(r0 + 8 * RST + 16);
                }
                #pragma unroll
                for (int mi = 0; mi < 4; mi++)
                    #pragma unroll
                    for (int ni = 0; ni < 8; ni++)
                        mma_bf16(acc[mi][ni], al[mi], bh[ni]);   // lo*hi
            }
        }
        __syncthreads();
    }

    float* Pl = P + (size_t)kh * NN * NCOL;
    #pragma unroll
    for (int mi = 0; mi < 4; mi++) {
        const size_t r = (size_t)(m0 + wm + mi * 16 + g);
        #pragma unroll
        for (int ni = 0; ni < 8; ni++) {
            const int c = wn + ni * 8 + 2 * t;
            *(float2*)&Pl[r * NCOL + c] = make_float2(acc[mi][ni][0], acc[mi][ni][1]);
            *(float2*)&Pl[(r + 8) * NCOL + c] = make_float2(acc[mi][ni][2], acc[mi][ni][3]);
        }
    }
}

// ---- out[b][m][g] = relu( sum_f (P0+P1)[m][b*64+f] * W[f][g] ) ----
// block: 64 rows; thread: 4 rows x 16 cols; H in per-batch smem planes,
// W read directly from global (L1-resident, 16B-aligned float4).
#define HPL 4360                 // H plane stride floats (64*68 + 8)
#define RED_SMEM (4 * HPL * 4)
__global__ __launch_bounds__(256) void reduce_w_kernel(
    const float* __restrict__ W, float* __restrict__ Zout)
{
    extern __shared__ char smemc[];
    float* Hs = (float*)smemc;                // [b][row][fp]: b*HPL + row*68 + fp

    const int tid = threadIdx.x;
    const int m0 = blockIdx.x * 64;
    const float* P0 = g_P[0];
    const float* P1 = g_P[1];

    for (int i = tid; i < 64 * 64; i += 256) {     // float4 sites
        int row = i >> 6, cq = i & 63;
        size_t gg = (size_t)(m0 + row) * NCOL + cq * 4;
        float4 a = *(const float4*)&P0[gg];
        float4 b4 = *(const float4*)&P1[gg];
        int b = cq >> 4, fp = (cq & 15) * 4;
        *(float4*)&Hs[b * HPL + row * 68 + fp] =
            make_float4(a.x + b4.x, a.y + b4.y, a.z + b4.z, a.w + b4.w);
    }
    __syncthreads();

    const int rg = tid >> 4;            // 0..15 -> rows rg*4..rg*4+3
    const int gq = tid & 15;
    const int b = gq >> 2, fh = gq & 3;

    float acc[4][16] = {};
    const float* hb = &Hs[b * HPL + rg * 4 * 68];
    const float4* wbase = (const float4*)(W + fh * 16);   // row fp: W[fp*64 + fh*16 ..]

    #pragma unroll 8
    for (int fp = 0; fp < 64; fp++) {
        float h0 = hb[fp], h1 = hb[68 + fp], h2 = hb[136 + fp], h3 = hb[204 + fp];
        const float4* wr = wbase + fp * 16;   // 64 floats per row = 16 float4
        float4 w0 = __ldg(wr);
        float4 w1 = __ldg(wr + 1);
        float4 w2 = __ldg(wr + 2);
        float4 w3 = __ldg(wr + 3);
        float wv[16] = {w0.x, w0.y, w0.z, w0.w, w1.x, w1.y, w1.z, w1.w,
                        w2.x, w2.y, w2.z, w2.w, w3.x, w3.y, w3.z, w3.w};
        #pragma unroll
        for (int j = 0; j < 16; j++) {
            acc[0][j] += h0 * wv[j];
            acc[1][j] += h1 * wv[j];
            acc[2][j] += h2 * wv[j];
            acc[3][j] += h3 * wv[j];
        }
    }

    #pragma unroll
    for (int rr = 0; rr < 4; rr++) {
        float* op = Zout + ((size_t)b * NN + m0 + rg * 4 + rr) * FF + fh * 16;
        #pragma unroll
        for (int j = 0; j < 16; j += 4)
            *(float4*)&op[j] = make_float4(
                fmaxf(acc[rr][j], 0.f), fmaxf(acc[rr][j + 1], 0.f),
                fmaxf(acc[rr][j + 2], 0.f), fmaxf(acc[rr][j + 3], 0.f));
    }
}

extern "C" void kernel_launch(void* const* d_in, const int* in_sizes, int n_in,
                              void* d_out, int out_size)
{
    const float* x   = (const float*)d_in[0];
    const float* net = (const float*)d_in[2];
    const float* A   = (const float*)d_in[3];
    float* out       = (float*)d_out;

    float *P = nullptr, *Zmid = nullptr;
    cudaGetSymbolAddress((void**)&P, g_P);
    cudaGetSymbolAddress((void**)&Zmid, g_Zmid);

    cudaFuncSetAttribute(gemm_kernel,
                         cudaFuncAttributeMaxDynamicSharedMemorySize, GEMM_SMEM);
    cudaFuncSetAttribute(reduce_w_kernel,
                         cudaFuncAttributeMaxDynamicSharedMemorySize, RED_SMEM);

    dim3 ggrid(NN / MT, 2);
    dim3 zgrid(NN / 64, BB);

    split_a_kernel<<<4096, 256>>>(A);
    // layer 0
    split_z_kernel<<<zgrid, 256>>>(x);
    gemm_kernel<<<ggrid, 256, GEMM_SMEM>>>(P);
    reduce_w_kernel<<<NN / 64, 256, RED_SMEM>>>(net, Zmid);
    // layer 1
    split_z_kernel<<<zgrid, 256>>>(Zmid);
    gemm_kernel<<<ggrid, 256, GEMM_SMEM>>>(P);
    reduce_w_kernel<<<NN / 64, 256, RED_SMEM>>>(net + FF * FF, out);
}

// round 9
// speedup vs baseline: 5.4324x; 1.0154x over previous
#include <cuda_runtime.h>
#include <cuda_bf16.h>
#include <cstdint>

#define NN 8192
#define FF 64
#define BB 4
#define NCOL 256             // fused N = BB*FF
#define KHALF 4096
#define KT 32
#define NITER (KHALF / KT)   // 128
#define MT 128
#define RST 80               // smem row stride bytes

__device__ unsigned short g_A0[(size_t)NN * NN];
__device__ unsigned short g_A1[(size_t)NN * NN];
__device__ unsigned short g_Z0[(size_t)NCOL * NN];   // [n=b*64+f][k]
__device__ unsigned short g_Z1s[(size_t)NCOL * NN];
__device__ float g_P[2][(size_t)NN * NCOL];

// gemm smem per buffer: Ahi(10240) Alo(10240) Bhi(10240) Blo(10240) = 40960; x2
#define BUFB 40960
#define GEMM_SMEM (2 * BUFB)

__device__ __forceinline__ void cp16(uint32_t dst, const void* gsrc) {
    asm volatile("cp.async.cg.shared.global [%0], [%1], 16;\n" :: "r"(dst), "l"(gsrc));
}
__device__ __forceinline__ void ldm4(uint32_t& r0, uint32_t& r1, uint32_t& r2,
                                     uint32_t& r3, uint32_t a) {
    asm volatile("ldmatrix.sync.aligned.m8n8.x4.shared.b16 {%0,%1,%2,%3}, [%4];"
                 : "=r"(r0), "=r"(r1), "=r"(r2), "=r"(r3) : "r"(a));
}
__device__ __forceinline__ void mma_bf16(float* d, const uint32_t* a, const uint32_t* b) {
    asm volatile(
        "mma.sync.aligned.m16n8k16.row.col.f32.bf16.bf16.f32 "
        "{%0,%1,%2,%3},{%4,%5,%6,%7},{%8,%9},{%0,%1,%2,%3};"
        : "+f"(d[0]), "+f"(d[1]), "+f"(d[2]), "+f"(d[3])
        : "r"(a[0]), "r"(a[1]), "r"(a[2]), "r"(a[3]), "r"(b[0]), "r"(b[1]));
}
__device__ __forceinline__ void bsplit(float x, unsigned short& hi, unsigned short& lo) {
    __nv_bfloat16 h = __float2bfloat16_rn(x);
    float r = x - __bfloat162float(h);
    __nv_bfloat16 l = __float2bfloat16_rn(r);
    hi = *(unsigned short*)&h;
    lo = *(unsigned short*)&l;
}

// ---- split A (fp32 -> bf16 hi/lo), once ----
__global__ __launch_bounds__(256) void split_a_kernel(const float* __restrict__ A)
{
    size_t i4 = (size_t)blockIdx.x * 256 + threadIdx.x;
    const size_t n4 = (size_t)NN * NN / 4;
    size_t stride = (size_t)gridDim.x * 256;
    for (; i4 < n4; i4 += stride) {
        float4 v = ((const float4*)A)[i4];
        ushort4 h, l;
        bsplit(v.x, h.x, l.x); bsplit(v.y, h.y, l.y);
        bsplit(v.z, h.z, l.z); bsplit(v.w, h.w, l.w);
        ((ushort4*)g_A0)[i4] = h;
        ((ushort4*)g_A1)[i4] = l;
    }
}

// ---- split + transpose x: [b][k][f] fp32 -> [b*64+f][k] bf16 hi/lo (layer 0 in) ----
__global__ __launch_bounds__(256) void split_z_kernel(const float* __restrict__ Zin)
{
    __shared__ float s[64 * 65];
    const int b = blockIdx.y;
    const int k0 = blockIdx.x * 64;
    const int tid = threadIdx.x;
    #pragma unroll
    for (int i = 0; i < 16; i++) {
        int idx = tid + i * 256;
        int kr = idx >> 6, f = idx & 63;
        s[kr * 65 + f] = Zin[((size_t)b * NN + k0 + kr) * FF + f];
    }
    __syncthreads();
    #pragma unroll
    for (int i = 0; i < 16; i++) {
        int idx = tid + i * 256;
        int f = idx >> 6, kl = idx & 63;
        unsigned short h, l;
        bsplit(s[kl * 65 + f], h, l);
        size_t o = (size_t)(b * FF + f) * NN + k0 + kl;
        g_Z0[o] = h;
        g_Z1s[o] = l;
    }
}

// ---- GEMM: P[kh] = A[m-tile, khalf] @ Zfused  (3-product bf16 split) ----
// CTA 128M x 128N, 4 warps (64x64 each), 2 CTAs/SM, ldmatrix fragments.
__global__ __launch_bounds__(128, 2) void gemm_kernel(float* __restrict__ P)
{
    extern __shared__ char smem[];
    const uint32_t sb = (uint32_t)__cvta_generic_to_shared(smem);
    const int tid = threadIdx.x;
    const int lane = tid & 31;
    const int warp = tid >> 5;
    const int g = lane >> 2;
    const int t = lane & 3;
    const int wm = (warp & 1) * 64;
    const int wn = (warp >> 1) * 64;

    const int m0 = blockIdx.x * MT;
    const int n0 = blockIdx.y * 128;
    const int kh = blockIdx.z;
    const size_t kbase = (size_t)kh * KHALF;

    // ldmatrix per-lane address offsets (within a tile)
    const uint32_t aoff = (uint32_t)(wm + (lane & 15)) * RST + ((lane & 16) ? 16 : 0);
    const uint32_t boff = (uint32_t)(wn + (lane & 7) + ((lane & 16) ? 8 : 0)) * RST +
                          ((lane & 8) ? 16 : 0);

    float acc[4][8][4] = {};

    auto load_tile = [&](int buf, int kt) {
        const size_t k0 = kbase + (size_t)kt * KT;
        const uint32_t d0 = sb + buf * BUFB;
        #pragma unroll
        for (int s = 0; s < 2; s++) {
            const unsigned short* src = s ? g_A1 : g_A0;
            #pragma unroll
            for (int i = 0; i < 4; i++) {
                int idx = tid + i * 128;          // 0..511
                int r = idx >> 2, c = idx & 3;
                cp16(d0 + s * 10240 + r * RST + c * 16,
                     src + (size_t)(m0 + r) * NN + k0 + c * 8);
            }
        }
        #pragma unroll
        for (int s = 0; s < 2; s++) {
            const unsigned short* src = s ? g_Z1s : g_Z0;
            #pragma unroll
            for (int i = 0; i < 4; i++) {
                int idx = tid + i * 128;
                int r = idx >> 2, c = idx & 3;
                cp16(d0 + 20480 + s * 10240 + r * RST + c * 16,
                     src + (size_t)(n0 + r) * NN + k0 + c * 8);
            }
        }
    };

    load_tile(0, 0);
    asm volatile("cp.async.commit_group;\n" ::);

    for (int kt = 0; kt < NITER; kt++) {
        const int buf = kt & 1;
        if (kt + 1 < NITER) {
            load_tile(buf ^ 1, kt + 1);
            asm volatile("cp.async.commit_group;\n" ::);
            asm volatile("cp.async.wait_group 1;\n" ::);
        } else {
            asm volatile("cp.async.wait_group 0;\n" ::);
        }
        __syncthreads();

        const uint32_t abase = sb + buf * BUFB;
        #pragma unroll
        for (int kk = 0; kk < 2; kk++) {
            const uint32_t kbyte = kk * 32;
            const uint32_t aHi = abase + aoff + kbyte;
            const uint32_t aLo = aHi + 10240;
            const uint32_t bHi = abase + 20480 + boff + kbyte;
            const uint32_t bLo = bHi + 10240;

            uint32_t ah[4][4], bh[8][2];
            #pragma unroll
            for (int mi = 0; mi < 4; mi++)
                ldm4(ah[mi][0], ah[mi][1], ah[mi][2], ah[mi][3], aHi + mi * 16 * RST);
            #pragma unroll
            for (int p = 0; p < 4; p++)
                ldm4(bh[2 * p][0], bh[2 * p][1], bh[2 * p + 1][0], bh[2 * p + 1][1],
                     bHi + p * 16 * RST);
            #pragma unroll
            for (int mi = 0; mi < 4; mi++)
                #pragma unroll
                for (int ni = 0; ni < 8; ni++)
                    mma_bf16(acc[mi][ni], ah[mi], bh[ni]);   // hi*hi
            {
                uint32_t bl[8][2];
                #pragma unroll
                for (int p = 0; p < 4; p++)
                    ldm4(bl[2 * p][0], bl[2 * p][1], bl[2 * p + 1][0], bl[2 * p + 1][1],
                         bLo + p * 16 * RST);
                #pragma unroll
                for (int mi = 0; mi < 4; mi++)
                    #pragma unroll
                    for (int ni = 0; ni < 8; ni++)
                        mma_bf16(acc[mi][ni], ah[mi], bl[ni]);   // hi*lo
            }
            {
                uint32_t al[4][4];
                #pragma unroll
                for (int mi = 0; mi < 4; mi++)
                    ldm4(al[mi][0], al[mi][1], al[mi][2], al[mi][3], aLo + mi * 16 * RST);
                #pragma unroll
                for (int mi = 0; mi < 4; mi++)
                    #pragma unroll
                    for (int ni = 0; ni < 8; ni++)
                        mma_bf16(acc[mi][ni], al[mi], bh[ni]);   // lo*hi
            }
        }
        __syncthreads();
    }

    float* Pl = P + (size_t)kh * NN * NCOL;
    #pragma unroll
    for (int mi = 0; mi < 4; mi++) {
        const size_t r = (size_t)(m0 + wm + mi * 16 + g);
        #pragma unroll
        for (int ni = 0; ni < 8; ni++) {
            const int c = n0 + wn + ni * 8 + 2 * t;
            *(float2*)&Pl[r * NCOL + c] = make_float2(acc[mi][ni][0], acc[mi][ni][1]);
            *(float2*)&Pl[(r + 8) * NCOL + c] = make_float2(acc[mi][ni][2], acc[mi][ni][3]);
        }
    }
}

// ---- shared reduce compute: H = P0+P1 (64 rows), acc = relu(H @ W) ----
#define HPL 4360                 // H plane stride floats
#define RED_SMEM 73728           // max(Hs 69760, T 73728)

__device__ __forceinline__ void reduce_compute(
    float* Hs, const float* __restrict__ W, int m0, int tid, float acc[4][16],
    int& b_out, int& rg_out, int& fh_out)
{
    const float* P0 = g_P[0];
    const float* P1 = g_P[1];
    for (int i = tid; i < 64 * 64; i += 256) {
        int row = i >> 6, cq = i & 63;
        size_t gg = (size_t)(m0 + row) * NCOL + cq * 4;
        float4 a = *(const float4*)&P0[gg];
        float4 b4 = *(const float4*)&P1[gg];
        int b = cq >> 4, fp = (cq & 15) * 4;
        *(float4*)&Hs[b * HPL + row * 68 + fp] =
            make_float4(a.x + b4.x, a.y + b4.y, a.z + b4.z, a.w + b4.w);
    }
    __syncthreads();

    const int rg = tid >> 4;
    const int gq = tid & 15;
    const int b = gq >> 2, fh = gq & 3;
    b_out = b; rg_out = rg; fh_out = fh;

    const float* hb = &Hs[b * HPL + rg * 4 * 68];
    const float4* wbase = (const float4*)(W + fh * 16);

    #pragma unroll 8
    for (int fp = 0; fp < 64; fp++) {
        float h0 = hb[fp], h1 = hb[68 + fp], h2 = hb[136 + fp], h3 = hb[204 + fp];
        const float4* wr = wbase + fp * 16;
        float4 w0 = __ldg(wr), w1 = __ldg(wr + 1), w2 = __ldg(wr + 2), w3 = __ldg(wr + 3);
        float wv[16] = {w0.x, w0.y, w0.z, w0.w, w1.x, w1.y, w1.z, w1.w,
                        w2.x, w2.y, w2.z, w2.w, w3.x, w3.y, w3.z, w3.w};
        #pragma unroll
        for (int j = 0; j < 16; j++) {
            acc[0][j] += h0 * wv[j];
            acc[1][j] += h1 * wv[j];
            acc[2][j] += h2 * wv[j];
            acc[3][j] += h3 * wv[j];
        }
    }
    #pragma unroll
    for (int rr = 0; rr < 4; rr++)
        #pragma unroll
        for (int j = 0; j < 16; j++)
            acc[rr][j] = fmaxf(acc[rr][j], 0.f);
}

// final layer: write fp32 output
__global__ __launch_bounds__(256) void reduce_w_kernel(
    const float* __restrict__ W, float* __restrict__ Zout)
{
    extern __shared__ char smemc[];
    float* Hs = (float*)smemc;
    const int tid = threadIdx.x;
    const int m0 = blockIdx.x * 64;
    float acc[4][16] = {};
    int b, rg, fh;
    reduce_compute(Hs, W, m0, tid, acc, b, rg, fh);

    #pragma unroll
    for (int rr = 0; rr < 4; rr++) {
        float* op = Zout + ((size_t)b * NN + m0 + rg * 4 + rr) * FF + fh * 16;
        #pragma unroll
        for (int j = 0; j < 16; j += 4)
            *(float4*)&op[j] = make_float4(acc[rr][j], acc[rr][j + 1],
                                           acc[rr][j + 2], acc[rr][j + 3]);
    }
}

// mid layer: write bf16 hi/lo splits in transposed [n][k] layout
__global__ __launch_bounds__(256) void reduce_w_split_kernel(const float* __restrict__ W)
{
    extern __shared__ char smemc[];
    float* Hs = (float*)smemc;
    const int tid = threadIdx.x;
    const int m0 = blockIdx.x * 64;
    float acc[4][16] = {};
    int b, rg, fh;
    reduce_compute(Hs, W, m0, tid, acc, b, rg, fh);
    __syncthreads();     // done with Hs; reuse as transpose buffer

    unsigned short* Th = (unsigned short*)smemc;             // [256][72]
    unsigned short* Tl = Th + 256 * 72;
    #pragma unroll
    for (int rr = 0; rr < 4; rr++) {
        int m = rg * 4 + rr;
        #pragma unroll
        for (int j = 0; j < 16; j++) {
            int n = b * 64 + fh * 16 + j;
            unsigned short h, l;
            bsplit(acc[rr][j], h, l);
            Th[n * 72 + m] = h;
            Tl[n * 72 + m] = l;
        }
    }
    __syncthreads();

    {
        int n = tid;     // 0..255
        const uint4* sh = (const uint4*)&Th[n * 72];
        const uint4* sl = (const uint4*)&Tl[n * 72];
        uint4* dh = (uint4*)&g_Z0[(size_t)n * NN + m0];
        uint4* dl = (uint4*)&g_Z1s[(size_t)n * NN + m0];
        #pragma unroll
        for (int i = 0; i < 8; i++) dh[i] = sh[i];
        #pragma unroll
        for (int i = 0; i < 8; i++) dl[i] = sl[i];
    }
}

extern "C" void kernel_launch(void* const* d_in, const int* in_sizes, int n_in,
                              void* d_out, int out_size)
{
    const float* x   = (const float*)d_in[0];
    const float* net = (const float*)d_in[2];
    const float* A   = (const float*)d_in[3];
    float* out       = (float*)d_out;

    float* P = nullptr;
    cudaGetSymbolAddress((void**)&P, g_P);

    cudaFuncSetAttribute(gemm_kernel,
                         cudaFuncAttributeMaxDynamicSharedMemorySize, GEMM_SMEM);
    cudaFuncSetAttribute(reduce_w_kernel,
                         cudaFuncAttributeMaxDynamicSharedMemorySize, RED_SMEM);
    cudaFuncSetAttribute(reduce_w_split_kernel,
                         cudaFuncAttributeMaxDynamicSharedMemorySize, RED_SMEM);

    dim3 ggrid(NN / MT, 2, 2);
    dim3 zgrid(NN / 64, BB);

    split_a_kernel<<<4096, 256>>>(A);
    // layer 0
    split_z_kernel<<<zgrid, 256>>>(x);
    gemm_kernel<<<ggrid, 128, GEMM_SMEM>>>(P);
    reduce_w_split_kernel<<<NN / 64, 256, RED_SMEM>>>(net);   // -> g_Z0/g_Z1s
    // layer 1
    gemm_kernel<<<ggrid, 128, GEMM_SMEM>>>(P);
    reduce_w_kernel<<<NN / 64, 256, RED_SMEM>>>(net + FF * FF, out);
}

// round 10
// speedup vs baseline: 5.8202x; 1.0714x over previous
#include <cuda_runtime.h>
#include <cuda_bf16.h>
#include <cstdint>

#define NN 8192
#define FF 64
#define BB 4
#define NCOL 256
#define KHALF 4096
#define KT 32
#define NITER (KHALF / KT)   // 128
#define MT 128
#define RST 80               // smem row stride bytes

__device__ unsigned short g_Z0[(size_t)NCOL * NN];   // [n=b*64+f][k] bf16 hi
__device__ unsigned short g_Z1s[(size_t)NCOL * NN];  // lo
__device__ float g_P[2][(size_t)NN * NCOL];

// gemm smem per buffer: Ahi(10240) Alo(10240) Bhi(10240) Blo(10240) = 40960; x2
#define BUFB 40960
#define GEMM_SMEM (2 * BUFB)

__device__ __forceinline__ void cp16(uint32_t dst, const void* gsrc) {
    asm volatile("cp.async.cg.shared.global [%0], [%1], 16;\n" :: "r"(dst), "l"(gsrc));
}
__device__ __forceinline__ void ldm4(uint32_t& r0, uint32_t& r1, uint32_t& r2,
                                     uint32_t& r3, uint32_t a) {
    asm volatile("ldmatrix.sync.aligned.m8n8.x4.shared.b16 {%0,%1,%2,%3}, [%4];"
                 : "=r"(r0), "=r"(r1), "=r"(r2), "=r"(r3) : "r"(a));
}
__device__ __forceinline__ void mma_bf16(float* d, const uint32_t* a, const uint32_t* b) {
    asm volatile(
        "mma.sync.aligned.m16n8k16.row.col.f32.bf16.bf16.f32 "
        "{%0,%1,%2,%3},{%4,%5,%6,%7},{%8,%9},{%0,%1,%2,%3};"
        : "+f"(d[0]), "+f"(d[1]), "+f"(d[2]), "+f"(d[3])
        : "r"(a[0]), "r"(a[1]), "r"(a[2]), "r"(a[3]), "r"(b[0]), "r"(b[1]));
}
__device__ __forceinline__ uint32_t cvt2(float hi, float lo) {
    uint32_t r;
    asm("cvt.rn.bf16x2.f32 %0, %1, %2;" : "=r"(r) : "f"(hi), "f"(lo));
    return r;
}
__device__ __forceinline__ void bsplit(float x, unsigned short& hi, unsigned short& lo) {
    __nv_bfloat16 h = __float2bfloat16_rn(x);
    float r = x - __bfloat162float(h);
    __nv_bfloat16 l = __float2bfloat16_rn(r);
    hi = *(unsigned short*)&h;
    lo = *(unsigned short*)&l;
}

// ---- split + transpose x: [b][k][f] fp32 -> [b*64+f][k] bf16 hi/lo (layer 0) ----
__global__ __launch_bounds__(256) void split_z_kernel(const float* __restrict__ Zin)
{
    __shared__ float s[64 * 65];
    const int b = blockIdx.y;
    const int k0 = blockIdx.x * 64;
    const int tid = threadIdx.x;
    #pragma unroll
    for (int i = 0; i < 16; i++) {
        int idx = tid + i * 256;
        int kr = idx >> 6, f = idx & 63;
        s[kr * 65 + f] = Zin[((size_t)b * NN + k0 + kr) * FF + f];
    }
    __syncthreads();
    #pragma unroll
    for (int i = 0; i < 16; i++) {
        int idx = tid + i * 256;
        int f = idx >> 6, kl = idx & 63;
        unsigned short h, l;
        bsplit(s[kl * 65 + f], h, l);
        size_t o = (size_t)(b * FF + f) * NN + k0 + kl;
        g_Z0[o] = h;
        g_Z1s[o] = l;
    }
}

// ---- GEMM: P[kh] = A[m-tile, khalf] @ Zfused  (3-product bf16 split) ----
// A read as fp32, split in-register (no pre-split pass). CTA 128x128, 2 CTA/SM.
__global__ __launch_bounds__(128, 2) void gemm_kernel(
    const float* __restrict__ A, float* __restrict__ P)
{
    extern __shared__ char smem[];
    const uint32_t sb = (uint32_t)__cvta_generic_to_shared(smem);
    const int tid = threadIdx.x;
    const int lane = tid & 31;
    const int warp = tid >> 5;
    const int g = lane >> 2;
    const int t = lane & 3;
    const int wm = (warp & 1) * 64;
    const int wn = (warp >> 1) * 64;

    const int m0 = blockIdx.x * MT;
    const int n0 = blockIdx.y * 128;
    const int kh = blockIdx.z;
    const size_t kbase = (size_t)kh * KHALF;

    // A loader geometry: site idx = tid + i*128 -> row = tid>>3 + 16*i, c8 = tid&7
    const int ar = tid >> 3;
    const int ac8 = tid & 7;
    const float* Ab = A + (size_t)(m0 + ar) * NN + kbase + ac8 * 4;
    const uint32_t asts = ar * RST + ac8 * 8;

    const uint32_t aoff = (uint32_t)(wm + (lane & 15)) * RST + ((lane & 16) ? 16 : 0);
    const uint32_t boff = (uint32_t)(wn + (lane & 7) + ((lane & 16) ? 8 : 0)) * RST +
                          ((lane & 8) ? 16 : 0);

    float acc[4][8][4] = {};
    float4 av[8];

    auto ldgA = [&](int kt) {
        const float* p = Ab + (size_t)kt * KT;
        #pragma unroll
        for (int i = 0; i < 8; i++)
            av[i] = __ldg((const float4*)(p + (size_t)(16 * i) * NN));
    };
    auto stsA = [&](int buf) {
        const uint32_t d0 = sb + buf * BUFB + asts;
        #pragma unroll
        for (int i = 0; i < 8; i++) {
            float4 v = av[i];
            uint32_t h01 = cvt2(v.y, v.x);
            uint32_t h23 = cvt2(v.w, v.z);
            float r0 = v.x - __uint_as_float(h01 << 16);
            float r1 = v.y - __uint_as_float(h01 & 0xFFFF0000u);
            float r2 = v.z - __uint_as_float(h23 << 16);
            float r3 = v.w - __uint_as_float(h23 & 0xFFFF0000u);
            uint32_t l01 = cvt2(r1, r0);
            uint32_t l23 = cvt2(r3, r2);
            uint32_t off = d0 + i * 16 * RST;
            asm volatile("st.shared.v2.b32 [%0], {%1,%2};" :: "r"(off), "r"(h01), "r"(h23));
            asm volatile("st.shared.v2.b32 [%0+10240], {%1,%2};" :: "r"(off), "r"(l01), "r"(l23));
        }
    };
    auto loadB = [&](int buf, int kt) {
        const size_t k0 = kbase + (size_t)kt * KT;
        const uint32_t d0 = sb + buf * BUFB + 20480;
        #pragma unroll
        for (int s = 0; s < 2; s++) {
            const unsigned short* src = s ? g_Z1s : g_Z0;
            #pragma unroll
            for (int i = 0; i < 4; i++) {
                int idx = tid + i * 128;
                int r = idx >> 2, c = idx & 3;
                cp16(d0 + s * 10240 + r * RST + c * 16,
                     src + (size_t)(n0 + r) * NN + k0 + c * 8);
            }
        }
    };

    ldgA(0);
    loadB(0, 0);
    asm volatile("cp.async.commit_group;\n" ::);

    for (int kt = 0; kt < NITER; kt++) {
        const int buf = kt & 1;
        stsA(buf);                          // split regs (tile kt) -> smem
        if (kt + 1 < NITER) {
            ldgA(kt + 1);                   // overwrites av; lands during mma below
            loadB(buf ^ 1, kt + 1);
            asm volatile("cp.async.commit_group;\n" ::);
            asm volatile("cp.async.wait_group 1;\n" ::);
        } else {
            asm volatile("cp.async.wait_group 0;\n" ::);
        }
        __syncthreads();

        const uint32_t abase = sb + buf * BUFB;
        #pragma unroll
        for (int kk = 0; kk < 2; kk++) {
            const uint32_t kbyte = kk * 32;
            const uint32_t aHi = abase + aoff + kbyte;
            const uint32_t aLo = aHi + 10240;
            const uint32_t bHi = abase + 20480 + boff + kbyte;
            const uint32_t bLo = bHi + 10240;

            uint32_t ah[4][4], bh[8][2];
            #pragma unroll
            for (int mi = 0; mi < 4; mi++)
                ldm4(ah[mi][0], ah[mi][1], ah[mi][2], ah[mi][3], aHi + mi * 16 * RST);
            #pragma unroll
            for (int p = 0; p < 4; p++)
                ldm4(bh[2 * p][0], bh[2 * p][1], bh[2 * p + 1][0], bh[2 * p + 1][1],
                     bHi + p * 16 * RST);
            #pragma unroll
            for (int mi = 0; mi < 4; mi++)
                #pragma unroll
                for (int ni = 0; ni < 8; ni++)
                    mma_bf16(acc[mi][ni], ah[mi], bh[ni]);   // hi*hi
            {
                uint32_t bl[8][2];
                #pragma unroll
                for (int p = 0; p < 4; p++)
                    ldm4(bl[2 * p][0], bl[2 * p][1], bl[2 * p + 1][0], bl[2 * p + 1][1],
                         bLo + p * 16 * RST);
                #pragma unroll
                for (int mi = 0; mi < 4; mi++)
                    #pragma unroll
                    for (int ni = 0; ni < 8; ni++)
                        mma_bf16(acc[mi][ni], ah[mi], bl[ni]);   // hi*lo
            }
            {
                uint32_t al[4][4];
                #pragma unroll
                for (int mi = 0; mi < 4; mi++)
                    ldm4(al[mi][0], al[mi][1], al[mi][2], al[mi][3], aLo + mi * 16 * RST);
                #pragma unroll
                for (int mi = 0; mi < 4; mi++)
                    #pragma unroll
                    for (int ni = 0; ni < 8; ni++)
                        mma_bf16(acc[mi][ni], al[mi], bh[ni]);   // lo*hi
            }
        }
        __syncthreads();
    }

    float* Pl = P + (size_t)kh * NN * NCOL;
    #pragma unroll
    for (int mi = 0; mi < 4; mi++) {
        const size_t r = (size_t)(m0 + wm + mi * 16 + g);
        #pragma unroll
        for (int ni = 0; ni < 8; ni++) {
            const int c = n0 + wn + ni * 8 + 2 * t;
            *(float2*)&Pl[r * NCOL + c] = make_float2(acc[mi][ni][0], acc[mi][ni][1]);
            *(float2*)&Pl[(r + 8) * NCOL + c] = make_float2(acc[mi][ni][2], acc[mi][ni][3]);
        }
    }
}

// ---- reduce: per-(64 rows x 1 batch) block. acc = relu((P0+P1) @ W) ----
#define RED_SMEM 18560
__device__ __forceinline__ void reduce_compute2(
    float* Hs, const float* __restrict__ W, int m0, int b, int tid,
    float acc[16], int& row_o, int& fh_o)
{
    const float* P0 = g_P[0];
    const float* P1 = g_P[1];
    #pragma unroll
    for (int i = tid; i < 64 * 16; i += 256) {
        int r = i >> 4, q = i & 15;
        size_t gg = (size_t)(m0 + r) * NCOL + b * 64 + q * 4;
        float4 a = *(const float4*)&P0[gg];
        float4 b4 = *(const float4*)&P1[gg];
        *(float4*)&Hs[r * 68 + q * 4] =
            make_float4(a.x + b4.x, a.y + b4.y, a.z + b4.z, a.w + b4.w);
    }
    __syncthreads();

    const int row = tid >> 2;
    const int fh = tid & 3;
    row_o = row; fh_o = fh;
    const float* hb = &Hs[row * 68];
    const float4* wbase = (const float4*)(W + fh * 16);

    #pragma unroll 8
    for (int fp = 0; fp < 64; fp++) {
        float h = hb[fp];
        const float4* wr = wbase + fp * 16;
        float4 w0 = __ldg(wr), w1 = __ldg(wr + 1), w2 = __ldg(wr + 2), w3 = __ldg(wr + 3);
        acc[0] += h * w0.x;  acc[1] += h * w0.y;  acc[2] += h * w0.z;  acc[3] += h * w0.w;
        acc[4] += h * w1.x;  acc[5] += h * w1.y;  acc[6] += h * w1.z;  acc[7] += h * w1.w;
        acc[8] += h * w2.x;  acc[9] += h * w2.y;  acc[10] += h * w2.z; acc[11] += h * w2.w;
        acc[12] += h * w3.x; acc[13] += h * w3.y; acc[14] += h * w3.z; acc[15] += h * w3.w;
    }
    #pragma unroll
    for (int j = 0; j < 16; j++) acc[j] = fmaxf(acc[j], 0.f);
}

__global__ __launch_bounds__(256) void reduce_w_kernel(
    const float* __restrict__ W, float* __restrict__ Zout)
{
    extern __shared__ char smemc[];
    float* Hs = (float*)smemc;
    const int tid = threadIdx.x;
    const int m0 = blockIdx.x * 64;
    const int b = blockIdx.y;
    float acc[16] = {};
    int row, fh;
    reduce_compute2(Hs, W, m0, b, tid, acc, row, fh);

    float* op = Zout + ((size_t)b * NN + m0 + row) * FF + fh * 16;
    #pragma unroll
    for (int j = 0; j < 16; j += 4)
        *(float4*)&op[j] = make_float4(acc[j], acc[j + 1], acc[j + 2], acc[j + 3]);
}

// mid layer: write bf16 hi/lo splits transposed [n][k] -> g_Z0/g_Z1s
__global__ __launch_bounds__(256) void reduce_w_split_kernel(const float* __restrict__ W)
{
    extern __shared__ char smemc[];
    float* Hs = (float*)smemc;
    const int tid = threadIdx.x;
    const int m0 = blockIdx.x * 64;
    const int b = blockIdx.y;
    float acc[16] = {};
    int row, fh;
    reduce_compute2(Hs, W, m0, b, tid, acc, row, fh);
    __syncthreads();     // Hs dead; reuse as transpose buffers

    unsigned short* Th = (unsigned short*)smemc;   // [64][72]
    unsigned short* Tl = Th + 64 * 72;
    #pragma unroll
    for (int j = 0; j < 16; j++) {
        int n = fh * 16 + j;
        unsigned short h, l;
        bsplit(acc[j], h, l);
        Th[n * 72 + row] = h;
        Tl[n * 72 + row] = l;
    }
    __syncthreads();

    const int nq = tid >> 2;      // local n 0..63
    const int q = tid & 3;        // 16-short chunk 0..3
    const uint4* sh = (const uint4*)&Th[nq * 72 + q * 16];
    const uint4* sl = (const uint4*)&Tl[nq * 72 + q * 16];
    uint4* dh = (uint4*)&g_Z0[(size_t)(b * 64 + nq) * NN + m0 + q * 16];
    uint4* dl = (uint4*)&g_Z1s[(size_t)(b * 64 + nq) * NN + m0 + q * 16];
    dh[0] = sh[0]; dh[1] = sh[1];
    dl[0] = sl[0]; dl[1] = sl[1];
}

extern "C" void kernel_launch(void* const* d_in, const int* in_sizes, int n_in,
                              void* d_out, int out_size)
{
    const float* x   = (const float*)d_in[0];
    const float* net = (const float*)d_in[2];
    const float* A   = (const float*)d_in[3];
    float* out       = (float*)d_out;

    float* P = nullptr;
    cudaGetSymbolAddress((void**)&P, g_P);

    cudaFuncSetAttribute(gemm_kernel,
                         cudaFuncAttributeMaxDynamicSharedMemorySize, GEMM_SMEM);
    cudaFuncSetAttribute(reduce_w_kernel,
                         cudaFuncAttributeMaxDynamicSharedMemorySize, RED_SMEM);
    cudaFuncSetAttribute(reduce_w_split_kernel,
                         cudaFuncAttributeMaxDynamicSharedMemorySize, RED_SMEM);

    dim3 ggrid(NN / MT, 2, 2);
    dim3 zgrid(NN / 64, BB);
    dim3 rgrid(NN / 64, BB);

    // layer 0
    split_z_kernel<<<zgrid, 256>>>(x);
    gemm_kernel<<<ggrid, 128, GEMM_SMEM>>>(A, P);
    reduce_w_split_kernel<<<rgrid, 256, RED_SMEM>>>(net);     // -> g_Z0/g_Z1s
    // layer 1
    gemm_kernel<<<ggrid, 128, GEMM_SMEM>>>(A, P);
    reduce_w_kernel<<<rgrid, 256, RED_SMEM>>>(net + FF * FF, out);
}

// round 11
// speedup vs baseline: 5.8362x; 1.0028x over previous
#include <cuda_runtime.h>
#include <cuda_bf16.h>
#include <cstdint>

#define NN 8192
#define FF 64
#define BB 4
#define NCOL 256
#define KHALF 4096
#define KT 32
#define NITER (KHALF / KT)   // 128
#define MT 128
#define RST 80               // smem row stride bytes

__device__ unsigned short g_Z0[(size_t)NCOL * NN];   // [n=b*64+f][k] bf16 hi
__device__ unsigned short g_Z1s[(size_t)NCOL * NN];  // lo
__device__ float g_P[2][(size_t)NN * NCOL];

// gemm smem per buffer: Ahi(10240) Alo(10240) Bhi(10240) Blo(10240) = 40960; x2
#define BUFB 40960
#define GEMM_SMEM (2 * BUFB)

__device__ __forceinline__ void cp16(uint32_t dst, const void* gsrc) {
    asm volatile("cp.async.cg.shared.global [%0], [%1], 16;\n" :: "r"(dst), "l"(gsrc));
}
__device__ __forceinline__ void ldm4(uint32_t& r0, uint32_t& r1, uint32_t& r2,
                                     uint32_t& r3, uint32_t a) {
    asm volatile("ldmatrix.sync.aligned.m8n8.x4.shared.b16 {%0,%1,%2,%3}, [%4];"
                 : "=r"(r0), "=r"(r1), "=r"(r2), "=r"(r3) : "r"(a));
}
__device__ __forceinline__ void mma_bf16(float* d, const uint32_t* a, const uint32_t* b) {
    asm volatile(
        "mma.sync.aligned.m16n8k16.row.col.f32.bf16.bf16.f32 "
        "{%0,%1,%2,%3},{%4,%5,%6,%7},{%8,%9},{%0,%1,%2,%3};"
        : "+f"(d[0]), "+f"(d[1]), "+f"(d[2]), "+f"(d[3])
        : "r"(a[0]), "r"(a[1]), "r"(a[2]), "r"(a[3]), "r"(b[0]), "r"(b[1]));
}
__device__ __forceinline__ uint32_t cvt2(float hi, float lo) {
    uint32_t r;
    asm("cvt.rn.bf16x2.f32 %0, %1, %2;" : "=r"(r) : "f"(hi), "f"(lo));
    return r;
}
__device__ __forceinline__ void bsplit(float x, unsigned short& hi, unsigned short& lo) {
    __nv_bfloat16 h = __float2bfloat16_rn(x);
    float r = x - __bfloat162float(h);
    __nv_bfloat16 l = __float2bfloat16_rn(r);
    hi = *(unsigned short*)&h;
    lo = *(unsigned short*)&l;
}

// ---- split + transpose x: [b][k][f] fp32 -> [b*64+f][k] bf16 hi/lo (layer 0) ----
__global__ __launch_bounds__(256) void split_z_kernel(const float* __restrict__ Zin)
{
    __shared__ float s[64 * 65];
    const int b = blockIdx.y;
    const int k0 = blockIdx.x * 64;
    const int tid = threadIdx.x;
    #pragma unroll
    for (int i = 0; i < 16; i++) {
        int idx = tid + i * 256;
        int kr = idx >> 6, f = idx & 63;
        s[kr * 65 + f] = Zin[((size_t)b * NN + k0 + kr) * FF + f];
    }
    __syncthreads();
    #pragma unroll
    for (int i = 0; i < 16; i++) {
        int idx = tid + i * 256;
        int f = idx >> 6, kl = idx & 63;
        unsigned short h, l;
        bsplit(s[kl * 65 + f], h, l);
        size_t o = (size_t)(b * FF + f) * NN + k0 + kl;
        g_Z0[o] = h;
        g_Z1s[o] = l;
    }
}

// ---- GEMM: P[kh] = A[m-tile, khalf] @ Zfused  (3-product bf16 split) ----
// A read as fp32, split in-register (no pre-split pass). CTA 128x128, 2 CTA/SM.
__global__ __launch_bounds__(128, 2) void gemm_kernel(
    const float* __restrict__ A, float* __restrict__ P)
{
    extern __shared__ char smem[];
    const uint32_t sb = (uint32_t)__cvta_generic_to_shared(smem);
    const int tid = threadIdx.x;
    const int lane = tid & 31;
    const int warp = tid >> 5;
    const int g = lane >> 2;
    const int t = lane & 3;
    const int wm = (warp & 1) * 64;
    const int wn = (warp >> 1) * 64;

    const int m0 = blockIdx.x * MT;
    const int n0 = blockIdx.y * 128;
    const int kh = blockIdx.z;
    const size_t kbase = (size_t)kh * KHALF;

    // A loader geometry: site idx = tid + i*128 -> row = tid>>3 + 16*i, c8 = tid&7
    const int ar = tid >> 3;
    const int ac8 = tid & 7;
    const float* Ab = A + (size_t)(m0 + ar) * NN + kbase + ac8 * 4;
    const uint32_t asts = ar * RST + ac8 * 8;

    const uint32_t aoff = (uint32_t)(wm + (lane & 15)) * RST + ((lane & 16) ? 16 : 0);
    const uint32_t boff = (uint32_t)(wn + (lane & 7) + ((lane & 16) ? 8 : 0)) * RST +
                          ((lane & 8) ? 16 : 0);

    float acc[4][8][4] = {};
    float4 av[8];

    auto ldgA = [&](int kt) {
        const float* p = Ab + (size_t)kt * KT;
        #pragma unroll
        for (int i = 0; i < 8; i++)
            av[i] = __ldg((const float4*)(p + (size_t)(16 * i) * NN));
    };
    auto stsA = [&](int buf) {
        const uint32_t d0 = sb + buf * BUFB + asts;
        #pragma unroll
        for (int i = 0; i < 8; i++) {
            float4 v = av[i];
            uint32_t h01 = cvt2(v.y, v.x);
            uint32_t h23 = cvt2(v.w, v.z);
            float r0 = v.x - __uint_as_float(h01 << 16);
            float r1 = v.y - __uint_as_float(h01 & 0xFFFF0000u);
            float r2 = v.z - __uint_as_float(h23 << 16);
            float r3 = v.w - __uint_as_float(h23 & 0xFFFF0000u);
            uint32_t l01 = cvt2(r1, r0);
            uint32_t l23 = cvt2(r3, r2);
            uint32_t off = d0 + i * 16 * RST;
            asm volatile("st.shared.v2.b32 [%0], {%1,%2};" :: "r"(off), "r"(h01), "r"(h23));
            asm volatile("st.shared.v2.b32 [%0+10240], {%1,%2};" :: "r"(off), "r"(l01), "r"(l23));
        }
    };
    auto loadB = [&](int buf, int kt) {
        const size_t k0 = kbase + (size_t)kt * KT;
        const uint32_t d0 = sb + buf * BUFB + 20480;
        #pragma unroll
        for (int s = 0; s < 2; s++) {
            const unsigned short* src = s ? g_Z1s : g_Z0;
            #pragma unroll
            for (int i = 0; i < 4; i++) {
                int idx = tid + i * 128;
                int r = idx >> 2, c = idx & 3;
                cp16(d0 + s * 10240 + r * RST + c * 16,
                     src + (size_t)(n0 + r) * NN + k0 + c * 8);
            }
        }
    };

    ldgA(0);
    loadB(0, 0);
    asm volatile("cp.async.commit_group;\n" ::);

    for (int kt = 0; kt < NITER; kt++) {
        const int buf = kt & 1;
        stsA(buf);                          // split regs (tile kt) -> smem
        if (kt + 1 < NITER) {
            ldgA(kt + 1);                   // overwrites av; lands during mma below
            loadB(buf ^ 1, kt + 1);
            asm volatile("cp.async.commit_group;\n" ::);
            asm volatile("cp.async.wait_group 1;\n" ::);
        } else {
            asm volatile("cp.async.wait_group 0;\n" ::);
        }
        __syncthreads();

        const uint32_t abase = sb + buf * BUFB;
        #pragma unroll
        for (int kk = 0; kk < 2; kk++) {
            const uint32_t kbyte = kk * 32;
            const uint32_t aHi = abase + aoff + kbyte;
            const uint32_t aLo = aHi + 10240;
            const uint32_t bHi = abase + 20480 + boff + kbyte;
            const uint32_t bLo = bHi + 10240;

            uint32_t ah[4][4], bh[8][2];
            #pragma unroll
            for (int mi = 0; mi < 4; mi++)
                ldm4(ah[mi][0], ah[mi][1], ah[mi][2], ah[mi][3], aHi + mi * 16 * RST);
            #pragma unroll
            for (int p = 0; p < 4; p++)
                ldm4(bh[2 * p][0], bh[2 * p][1], bh[2 * p + 1][0], bh[2 * p + 1][1],
                     bHi + p * 16 * RST);
            #pragma unroll
            for (int mi = 0; mi < 4; mi++)
                #pragma unroll
                for (int ni = 0; ni < 8; ni++)
                    mma_bf16(acc[mi][ni], ah[mi], bh[ni]);   // hi*hi
            {
                uint32_t bl[8][2];
                #pragma unroll
                for (int p = 0; p < 4; p++)
                    ldm4(bl[2 * p][0], bl[2 * p][1], bl[2 * p + 1][0], bl[2 * p + 1][1],
                         bLo + p * 16 * RST);
                #pragma unroll
                for (int mi = 0; mi < 4; mi++)
                    #pragma unroll
                    for (int ni = 0; ni < 8; ni++)
                        mma_bf16(acc[mi][ni], ah[mi], bl[ni]);   // hi*lo
            }
            {
                uint32_t al[4][4];
                #pragma unroll
                for (int mi = 0; mi < 4; mi++)
                    ldm4(al[mi][0], al[mi][1], al[mi][2], al[mi][3], aLo + mi * 16 * RST);
                #pragma unroll
                for (int mi = 0; mi < 4; mi++)
                    #pragma unroll
                    for (int ni = 0; ni < 8; ni++)
                        mma_bf16(acc[mi][ni], al[mi], bh[ni]);   // lo*hi
            }
        }
        __syncthreads();
    }

    float* Pl = P + (size_t)kh * NN * NCOL;
    #pragma unroll
    for (int mi = 0; mi < 4; mi++) {
        const size_t r = (size_t)(m0 + wm + mi * 16 + g);
        #pragma unroll
        for (int ni = 0; ni < 8; ni++) {
            const int c = n0 + wn + ni * 8 + 2 * t;
            *(float2*)&Pl[r * NCOL + c] = make_float2(acc[mi][ni][0], acc[mi][ni][1]);
            *(float2*)&Pl[(r + 8) * NCOL + c] = make_float2(acc[mi][ni][2], acc[mi][ni][3]);
        }
    }
}

// ---- reduce: per-(64 rows x 1 batch) block. acc = relu((P0+P1) @ W) ----
#define RED_SMEM 18560
__device__ __forceinline__ void reduce_compute2(
    float* Hs, const float* __restrict__ W, int m0, int b, int tid,
    float acc[16], int& row_o, int& fh_o)
{
    const float* P0 = g_P[0];
    const float* P1 = g_P[1];
    #pragma unroll
    for (int i = tid; i < 64 * 16; i += 256) {
        int r = i >> 4, q = i & 15;
        size_t gg = (size_t)(m0 + r) * NCOL + b * 64 + q * 4;
        float4 a = *(const float4*)&P0[gg];
        float4 b4 = *(const float4*)&P1[gg];
        *(float4*)&Hs[r * 68 + q * 4] =
            make_float4(a.x + b4.x, a.y + b4.y, a.z + b4.z, a.w + b4.w);
    }
    __syncthreads();

    const int row = tid >> 2;
    const int fh = tid & 3;
    row_o = row; fh_o = fh;
    const float* hb = &Hs[row * 68];
    const float4* wbase = (const float4*)(W + fh * 16);

    #pragma unroll 8
    for (int fp = 0; fp < 64; fp++) {
        float h = hb[fp];
        const float4* wr = wbase + fp * 16;
        float4 w0 = __ldg(wr), w1 = __ldg(wr + 1), w2 = __ldg(wr + 2), w3 = __ldg(wr + 3);
        acc[0] += h * w0.x;  acc[1] += h * w0.y;  acc[2] += h * w0.z;  acc[3] += h * w0.w;
        acc[4] += h * w1.x;  acc[5] += h * w1.y;  acc[6] += h * w1.z;  acc[7] += h * w1.w;
        acc[8] += h * w2.x;  acc[9] += h * w2.y;  acc[10] += h * w2.z; acc[11] += h * w2.w;
        acc[12] += h * w3.x; acc[13] += h * w3.y; acc[14] += h * w3.z; acc[15] += h * w3.w;
    }
    #pragma unroll
    for (int j = 0; j < 16; j++) acc[j] = fmaxf(acc[j], 0.f);
}

__global__ __launch_bounds__(256) void reduce_w_kernel(
    const float* __restrict__ W, float* __restrict__ Zout)
{
    extern __shared__ char smemc[];
    float* Hs = (float*)smemc;
    const int tid = threadIdx.x;
    const int m0 = blockIdx.x * 64;
    const int b = blockIdx.y;
    float acc[16] = {};
    int row, fh;
    reduce_compute2(Hs, W, m0, b, tid, acc, row, fh);

    float* op = Zout + ((size_t)b * NN + m0 + row) * FF + fh * 16;
    #pragma unroll
    for (int j = 0; j < 16; j += 4)
        *(float4*)&op[j] = make_float4(acc[j], acc[j + 1], acc[j + 2], acc[j + 3]);
}

// mid layer: write bf16 hi/lo splits transposed [n][k] -> g_Z0/g_Z1s
__global__ __launch_bounds__(256) void reduce_w_split_kernel(const float* __restrict__ W)
{
    extern __shared__ char smemc[];
    float* Hs = (float*)smemc;
    const int tid = threadIdx.x;
    const int m0 = blockIdx.x * 64;
    const int b = blockIdx.y;
    float acc[16] = {};
    int row, fh;
    reduce_compute2(Hs, W, m0, b, tid, acc, row, fh);
    __syncthreads();     // Hs dead; reuse as transpose buffers

    unsigned short* Th = (unsigned short*)smemc;   // [64][72]
    unsigned short* Tl = Th + 64 * 72;
    #pragma unroll
    for (int j = 0; j < 16; j++) {
        int n = fh * 16 + j;
        unsigned short h, l;
        bsplit(acc[j], h, l);
        Th[n * 72 + row] = h;
        Tl[n * 72 + row] = l;
    }
    __syncthreads();

    const int nq = tid >> 2;      // local n 0..63
    const int q = tid & 3;        // 16-short chunk 0..3
    const uint4* sh = (const uint4*)&Th[nq * 72 + q * 16];
    const uint4* sl = (const uint4*)&Tl[nq * 72 + q * 16];
    uint4* dh = (uint4*)&g_Z0[(size_t)(b * 64 + nq) * NN + m0 + q * 16];
    uint4* dl = (uint4*)&g_Z1s[(size_t)(b * 64 + nq) * NN + m0 + q * 16];
    dh[0] = sh[0]; dh[1] = sh[1];
    dl[0] = sl[0]; dl[1] = sl[1];
}

extern "C" void kernel_launch(void* const* d_in, const int* in_sizes, int n_in,
                              void* d_out, int out_size)
{
    const float* x   = (const float*)d_in[0];
    const float* net = (const float*)d_in[2];
    const float* A   = (const float*)d_in[3];
    float* out       = (float*)d_out;

    float* P = nullptr;
    cudaGetSymbolAddress((void**)&P, g_P);

    cudaFuncSetAttribute(gemm_kernel,
                         cudaFuncAttributeMaxDynamicSharedMemorySize, GEMM_SMEM);
    cudaFuncSetAttribute(reduce_w_kernel,
                         cudaFuncAttributeMaxDynamicSharedMemorySize, RED_SMEM);
    cudaFuncSetAttribute(reduce_w_split_kernel,
                         cudaFuncAttributeMaxDynamicSharedMemorySize, RED_SMEM);

    dim3 ggrid(NN / MT, 2, 2);
    dim3 zgrid(NN / 64, BB);
    dim3 rgrid(NN / 64, BB);

    // layer 0
    split_z_kernel<<<zgrid, 256>>>(x);
    gemm_kernel<<<ggrid, 128, GEMM_SMEM>>>(A, P);
    reduce_w_split_kernel<<<rgrid, 256, RED_SMEM>>>(net);     // -> g_Z0/g_Z1s
    // layer 1
    gemm_kernel<<<ggrid, 128, GEMM_SMEM>>>(A, P);
    reduce_w_kernel<<<rgrid, 256, RED_SMEM>>>(net + FF * FF, out);
}